// round 1
// baseline (speedup 1.0000x reference)
#include <cuda_runtime.h>
#include <cstdint>

#define KQW      50
#define NCH      128          // key/value channels
#define NBINS    4096         // (positive float bits) >> 19  -> [0, 4096)
#define CAND_CAP 16384
#define SEL_CAP  4096
#define MAXN     1048576
#define NB_DIST  608          // 152 SMs * 4 blocks

// ---- scratch (device globals; no runtime allocation) ----
__device__ float    g_w[MAXN];          // per-row weights (4 MB, L2-resident)
__device__ float    g_bsum[2048];       // per-block partial sums of weights
__device__ unsigned g_hist[NBINS];      // global histogram of weight bit-bins
__device__ float    g_wsum;             // total weight sum
__device__ unsigned g_thresh_bin;       // smallest bin with cum-count >= 50
__device__ unsigned g_ncand;            // candidate counter
__device__ int      g_cand[CAND_CAP];   // candidate row indices

// ------------------------------------------------------------------
// K0: zero counters/histogram (deterministic fresh state per launch)
// ------------------------------------------------------------------
__global__ void k_init() {
    int i = blockIdx.x * blockDim.x + threadIdx.x;
    if (i < NBINS) g_hist[i] = 0u;
    if (i < 2048)  g_bsum[i] = 0.f;
    if (i == 0) { g_ncand = 0u; g_thresh_bin = 0u; g_wsum = 0.f; }
}

// ------------------------------------------------------------------
// K1: the 512MB streaming pass.
// warp-per-row: lane l loads keys[row][4l..4l+3] as float4 (coalesced
// 512B per warp). xor-shuffle reduce -> every lane has the full d2.
// 4-row unroll for MLP; lanes 0..3 each commit one row (store + shared
// histogram atomic — 4 same-warp atomics fold into one warp-op).
// ------------------------------------------------------------------
__global__ void __launch_bounds__(256)
k_dist(const float* __restrict__ key, const float* __restrict__ keys, int n) {
    __shared__ unsigned hist[NBINS];
    __shared__ float    ssum[8];
    for (int i = threadIdx.x; i < NBINS; i += blockDim.x) hist[i] = 0u;
    __syncthreads();

    const int lane  = threadIdx.x & 31;
    const int wid   = threadIdx.x >> 5;
    const int gwarp = (blockIdx.x * blockDim.x + threadIdx.x) >> 5;
    const int nwarp = (gridDim.x * blockDim.x) >> 5;

    const float4* kp = reinterpret_cast<const float4*>(keys);
    const float4  kq = reinterpret_cast<const float4*>(key)[lane];

    float lsum = 0.f;
    int row = gwarp;

    for (; row + 3 * nwarp < n; row += 4 * nwarp) {
        float4 a = kp[(size_t)row * 32 + lane];
        float4 b = kp[(size_t)(row +     nwarp) * 32 + lane];
        float4 c = kp[(size_t)(row + 2 * nwarp) * 32 + lane];
        float4 d = kp[(size_t)(row + 3 * nwarp) * 32 + lane];

        float dx, dy, dz, dw;
        dx = kq.x - a.x; dy = kq.y - a.y; dz = kq.z - a.z; dw = kq.w - a.w;
        float s0 = dx*dx + dy*dy + dz*dz + dw*dw;
        dx = kq.x - b.x; dy = kq.y - b.y; dz = kq.z - b.z; dw = kq.w - b.w;
        float s1 = dx*dx + dy*dy + dz*dz + dw*dw;
        dx = kq.x - c.x; dy = kq.y - c.y; dz = kq.z - c.z; dw = kq.w - c.w;
        float s2 = dx*dx + dy*dy + dz*dz + dw*dw;
        dx = kq.x - d.x; dy = kq.y - d.y; dz = kq.z - d.z; dw = kq.w - d.w;
        float s3 = dx*dx + dy*dy + dz*dz + dw*dw;

        #pragma unroll
        for (int o = 16; o; o >>= 1) {
            s0 += __shfl_xor_sync(0xffffffffu, s0, o);
            s1 += __shfl_xor_sync(0xffffffffu, s1, o);
            s2 += __shfl_xor_sync(0xffffffffu, s2, o);
            s3 += __shfl_xor_sync(0xffffffffu, s3, o);
        }
        float w0 = 1.f / (s0 + 1e-3f);
        float w1 = 1.f / (s1 + 1e-3f);
        float w2 = 1.f / (s2 + 1e-3f);
        float w3 = 1.f / (s3 + 1e-3f);
        if (lane < 4) {
            float wv = (lane == 0) ? w0 : (lane == 1) ? w1 : (lane == 2) ? w2 : w3;
            g_w[row + lane * nwarp] = wv;
            atomicAdd(&hist[__float_as_uint(wv) >> 19], 1u);
        }
        if (lane == 0) lsum += (w0 + w1) + (w2 + w3);
    }
    for (; row < n; row += nwarp) {
        float4 a = kp[(size_t)row * 32 + lane];
        float dx = kq.x - a.x, dy = kq.y - a.y, dz = kq.z - a.z, dw = kq.w - a.w;
        float s0 = dx*dx + dy*dy + dz*dz + dw*dw;
        #pragma unroll
        for (int o = 16; o; o >>= 1) s0 += __shfl_xor_sync(0xffffffffu, s0, o);
        if (lane == 0) {
            float wv = 1.f / (s0 + 1e-3f);
            g_w[row] = wv;
            lsum += wv;
            atomicAdd(&hist[__float_as_uint(wv) >> 19], 1u);
        }
    }

    // deterministic block-level weight sum (lane0-only values)
    #pragma unroll
    for (int o = 16; o; o >>= 1) lsum += __shfl_xor_sync(0xffffffffu, lsum, o);
    if (lane == 0) ssum[wid] = lsum;
    __syncthreads();
    if (threadIdx.x == 0) {
        float t = 0.f;
        for (int i = 0; i < 8; i++) t += ssum[i];
        g_bsum[blockIdx.x] = t;
    }
    // merge sparse histogram into global
    for (int i = threadIdx.x; i < NBINS; i += blockDim.x) {
        unsigned cnt = hist[i];
        if (cnt) atomicAdd(&g_hist[i], cnt);
    }
}

// ------------------------------------------------------------------
// K2 (1 block): total weight sum (deterministic order) + threshold bin:
// smallest bin b* such that count(bins >= b*) >= 50.
// ------------------------------------------------------------------
__global__ void __launch_bounds__(256)
k_thresh(int nblocks) {
    __shared__ float    ss[256];
    __shared__ unsigned csum[256];

    float t = 0.f;
    for (int i = threadIdx.x; i < nblocks; i += 256) t += g_bsum[i];
    ss[threadIdx.x] = t;

    unsigned s = 0u;
    const int base = threadIdx.x * (NBINS / 256);   // 16 bins / thread
    #pragma unroll
    for (int i = 0; i < NBINS / 256; i++) s += g_hist[base + i];
    csum[threadIdx.x] = s;
    __syncthreads();

    if (threadIdx.x == 0) {
        float tot = 0.f;
        for (int i = 0; i < 256; i++) tot += ss[i];
        g_wsum = tot;

        unsigned cum = 0u;
        int chunk = 255;
        for (; chunk > 0; chunk--) {
            if (cum + csum[chunk] >= (unsigned)KQW) break;
            cum += csum[chunk];
        }
        int b = chunk * (NBINS / 256) + (NBINS / 256) - 1;
        for (;; b--) {
            if (b <= chunk * (NBINS / 256)) break;          // bottom of chunk
            if (cum + g_hist[b] >= (unsigned)KQW) break;
            cum += g_hist[b];
        }
        g_thresh_bin = (unsigned)(b < 0 ? 0 : b);
    }
}

// ------------------------------------------------------------------
// K3: compact indices with bin >= threshold (expected O(100) hits)
// ------------------------------------------------------------------
__global__ void __launch_bounds__(256)
k_compact(int n) {
    const unsigned tb = g_thresh_bin;
    const int stride = gridDim.x * blockDim.x;
    for (int i = blockIdx.x * blockDim.x + threadIdx.x; i < n; i += stride) {
        if ((__float_as_uint(g_w[i]) >> 19) >= tb) {
            unsigned p = atomicAdd(&g_ncand, 1u);
            if (p < CAND_CAP) g_cand[p] = i;
        }
    }
}

// ------------------------------------------------------------------
// K4 (1 block): exact top-50 by rank counting (value desc, index asc —
// identical tiebreak to jax.lax.top_k), then gather + weighted sum.
// rank is a bijection onto [0,50) so sel[] writes are conflict-free
// and deterministic regardless of candidate order.
// ------------------------------------------------------------------
__global__ void __launch_bounds__(256)
k_final(const float* __restrict__ values, float* __restrict__ out) {
    __shared__ float cw[SEL_CAP];
    __shared__ int   ci[SEL_CAP];
    __shared__ float sel_w[KQW];
    __shared__ int   sel_i[KQW];

    int nc = (int)min(g_ncand, (unsigned)CAND_CAP);
    if (nc > SEL_CAP) nc = SEL_CAP;

    for (int i = threadIdx.x; i < nc; i += blockDim.x) {
        int idx = g_cand[i];
        ci[i] = idx;
        cw[i] = g_w[idx];
    }
    for (int i = threadIdx.x; i < KQW; i += blockDim.x) { sel_w[i] = 0.f; sel_i[i] = 0; }
    __syncthreads();

    for (int i = threadIdx.x; i < nc; i += blockDim.x) {
        const float wi = cw[i];
        const int   ii = ci[i];
        int rank = 0;
        for (int j = 0; j < nc; j++) {
            float wj = cw[j];
            rank += (wj > wi) || (wj == wi && ci[j] < ii);
        }
        if (rank < KQW) { sel_w[rank] = wi; sel_i[rank] = ii; }
    }
    __syncthreads();

    const int ns = nc < KQW ? nc : KQW;
    const float inv = 1.f / g_wsum;
    if (threadIdx.x < NCH) {
        float a0 = 0.f, a1 = 0.f, a2 = 0.f, a3 = 0.f;
        int j = 0;
        for (; j + 3 < ns; j += 4) {
            a0 += sel_w[j]     * values[(size_t)sel_i[j]     * NCH + threadIdx.x];
            a1 += sel_w[j + 1] * values[(size_t)sel_i[j + 1] * NCH + threadIdx.x];
            a2 += sel_w[j + 2] * values[(size_t)sel_i[j + 2] * NCH + threadIdx.x];
            a3 += sel_w[j + 3] * values[(size_t)sel_i[j + 3] * NCH + threadIdx.x];
        }
        for (; j < ns; j++)
            a0 += sel_w[j] * values[(size_t)sel_i[j] * NCH + threadIdx.x];
        out[threadIdx.x] = ((a0 + a1) + (a2 + a3)) * inv;
    }
}

// ------------------------------------------------------------------
extern "C" void kernel_launch(void* const* d_in, const int* in_sizes, int n_in,
                              void* d_out, int out_size) {
    const float* key    = (const float*)d_in[0];
    const float* keys   = (const float*)d_in[1];
    const float* values = (const float*)d_in[2];
    float* out = (float*)d_out;

    const int n = in_sizes[1] / NCH;   // number of memory rows (1,000,000)

    k_init   <<<16, 256>>>();
    k_dist   <<<NB_DIST, 256>>>(key, keys, n);
    k_thresh <<<1, 256>>>(NB_DIST);
    k_compact<<<256, 256>>>(n);
    k_final  <<<1, 256>>>(values, out);
}

// round 2
// speedup vs baseline: 1.1996x; 1.1996x over previous
#include <cuda_runtime.h>
#include <cstdint>

#define KQW      50
#define NCH      128          // key/value channels
#define NBINS    4096         // (positive float bits) >> 19  -> [0, 4096)
#define CAND_CAP 16384
#define SEL_CAP  4096
#define MAXN     1048576
#define NB_DIST  608          // 152 SMs * 4 blocks

// ---- scratch (device globals, zero at module load; kernels self-clean) ----
__device__ float    g_w[MAXN];          // per-row weights (4 MB, L2-resident)
__device__ float    g_bsum[NB_DIST];    // per-block partial sums of weights
__device__ unsigned g_hist[NBINS];      // histogram of weight bit-bins
__device__ float    g_wsum;             // total weight sum
__device__ unsigned g_thresh_bin;       // smallest bin with top-count >= 50
__device__ unsigned g_ncand;            // candidate counter
__device__ int      g_cand[CAND_CAP];   // candidate row indices

// ------------------------------------------------------------------
// K1: the 512MB streaming pass. warp-per-row, lane l holds channels
// 4l..4l+3 as float4 (512B/warp coalesced). 4-row unroll with a
// software-prefetched double buffer (8 loads in flight). Reduction:
// 3 xor levels on all 4 sums, then per-lane select + 2 levels
// (14 SHFLs / 4 rows). Rows committed by lanes 0,8,16,24.
// ------------------------------------------------------------------
__device__ __forceinline__ void commit4(
    float4 a0, float4 a1, float4 a2, float4 a3,
    float4 kq, int row, int nwarp, int lane,
    unsigned* hist, float& lsum)
{
    float dx, dy, dz, dw;
    dx = kq.x - a0.x; dy = kq.y - a0.y; dz = kq.z - a0.z; dw = kq.w - a0.w;
    float s0 = dx*dx + dy*dy + dz*dz + dw*dw;
    dx = kq.x - a1.x; dy = kq.y - a1.y; dz = kq.z - a1.z; dw = kq.w - a1.w;
    float s1 = dx*dx + dy*dy + dz*dz + dw*dw;
    dx = kq.x - a2.x; dy = kq.y - a2.y; dz = kq.z - a2.z; dw = kq.w - a2.w;
    float s2 = dx*dx + dy*dy + dz*dz + dw*dw;
    dx = kq.x - a3.x; dy = kq.y - a3.y; dz = kq.z - a3.z; dw = kq.w - a3.w;
    float s3 = dx*dx + dy*dy + dz*dz + dw*dw;

    #pragma unroll
    for (int o = 16; o >= 4; o >>= 1) {
        s0 += __shfl_xor_sync(0xffffffffu, s0, o);
        s1 += __shfl_xor_sync(0xffffffffu, s1, o);
        s2 += __shfl_xor_sync(0xffffffffu, s2, o);
        s3 += __shfl_xor_sync(0xffffffffu, s3, o);
    }
    // lanes sharing (lane&3) now hold group partials; route row (lane>>3)
    const int g = lane >> 3;
    float t = s0;
    if (g == 1) t = s1;
    if (g == 2) t = s2;
    if (g == 3) t = s3;
    t += __shfl_xor_sync(0xffffffffu, t, 2);
    t += __shfl_xor_sync(0xffffffffu, t, 1);
    // lane 8r commits row r
    if ((lane & 7) == 0) {
        float wv = 1.f / (t + 1e-3f);
        g_w[row + g * nwarp] = wv;
        atomicAdd(&hist[__float_as_uint(wv) >> 19], 1u);
        lsum += wv;
    }
}

__global__ void __launch_bounds__(256, 4)
k_dist(const float* __restrict__ key, const float* __restrict__ keys, int n) {
    __shared__ unsigned hist[NBINS];
    __shared__ float    ssum[8];
    for (int i = threadIdx.x; i < NBINS; i += 256) hist[i] = 0u;
    __syncthreads();

    const int lane  = threadIdx.x & 31;
    const int wid   = threadIdx.x >> 5;
    const int gwarp = (blockIdx.x * 256 + threadIdx.x) >> 5;
    const int nwarp = (gridDim.x * 256) >> 5;
    const int step  = 4 * nwarp;

    const float4* kp = reinterpret_cast<const float4*>(keys);
    const float4  kq = reinterpret_cast<const float4*>(key)[lane];

    float lsum = 0.f;
    int row = gwarp;

    if (row + 3 * nwarp < n) {
        float4 a0 = __ldcs(&kp[(size_t)row * 32 + lane]);
        float4 a1 = __ldcs(&kp[(size_t)(row +     nwarp) * 32 + lane]);
        float4 a2 = __ldcs(&kp[(size_t)(row + 2 * nwarp) * 32 + lane]);
        float4 a3 = __ldcs(&kp[(size_t)(row + 3 * nwarp) * 32 + lane]);
        int nrow = row + step;
        while (nrow + 3 * nwarp < n) {
            float4 b0 = __ldcs(&kp[(size_t)nrow * 32 + lane]);
            float4 b1 = __ldcs(&kp[(size_t)(nrow +     nwarp) * 32 + lane]);
            float4 b2 = __ldcs(&kp[(size_t)(nrow + 2 * nwarp) * 32 + lane]);
            float4 b3 = __ldcs(&kp[(size_t)(nrow + 3 * nwarp) * 32 + lane]);
            commit4(a0, a1, a2, a3, kq, row, nwarp, lane, hist, lsum);
            a0 = b0; a1 = b1; a2 = b2; a3 = b3;
            row = nrow; nrow += step;
        }
        commit4(a0, a1, a2, a3, kq, row, nwarp, lane, hist, lsum);
        row += step;
    }
    for (; row < n; row += nwarp) {
        float4 a = __ldcs(&kp[(size_t)row * 32 + lane]);
        float dx = kq.x - a.x, dy = kq.y - a.y, dz = kq.z - a.z, dw = kq.w - a.w;
        float s0 = dx*dx + dy*dy + dz*dz + dw*dw;
        #pragma unroll
        for (int o = 16; o; o >>= 1) s0 += __shfl_xor_sync(0xffffffffu, s0, o);
        if (lane == 0) {
            float wv = 1.f / (s0 + 1e-3f);
            g_w[row] = wv;
            lsum += wv;
            atomicAdd(&hist[__float_as_uint(wv) >> 19], 1u);
        }
    }

    // deterministic block-level weight sum
    #pragma unroll
    for (int o = 16; o; o >>= 1) lsum += __shfl_xor_sync(0xffffffffu, lsum, o);
    if (lane == 0) ssum[wid] = lsum;
    __syncthreads();
    if (threadIdx.x == 0) {
        float t = 0.f;
        for (int i = 0; i < 8; i++) t += ssum[i];
        g_bsum[blockIdx.x] = t;
    }
    // merge sparse histogram into global
    for (int i = threadIdx.x; i < NBINS; i += 256) {
        unsigned cnt = hist[i];
        if (cnt) atomicAdd(&g_hist[i], cnt);
    }
}

// ------------------------------------------------------------------
// K2 (1 block): total weight sum (fixed-tree, deterministic) +
// threshold bin: smallest bin b* with count(bins >= b*) >= 50.
// ------------------------------------------------------------------
__global__ void __launch_bounds__(256)
k_thresh(int nblocks) {
    __shared__ float    ss[256];
    __shared__ unsigned csum[256];
    const int tid = threadIdx.x;

    float t = 0.f;
    for (int i = tid; i < nblocks; i += 256) t += g_bsum[i];
    ss[tid] = t;

    unsigned s = 0u;
    const int base = tid * (NBINS / 256);   // 16 bins / thread
    #pragma unroll
    for (int i = 0; i < NBINS / 256; i++) s += g_hist[base + i];
    csum[tid] = s;
    __syncthreads();

    for (int o = 128; o; o >>= 1) {
        if (tid < o) ss[tid] += ss[tid + o];
        __syncthreads();
    }
    if (tid == 0) {
        g_wsum = ss[0];
        unsigned cum = 0u;
        int chunk = 255;
        for (; chunk > 0; chunk--) {
            if (cum + csum[chunk] >= (unsigned)KQW) break;
            cum += csum[chunk];
        }
        int b = chunk * (NBINS / 256) + (NBINS / 256) - 1;
        for (;; b--) {
            if (b <= chunk * (NBINS / 256)) break;
            if (cum + g_hist[b] >= (unsigned)KQW) break;
            cum += g_hist[b];
        }
        g_thresh_bin = (unsigned)(b < 0 ? 0 : b);
    }
}

// ------------------------------------------------------------------
// K3: compact indices with bin >= threshold. float4 over L2-resident
// g_w, ~1 vector load per thread. Also re-zeros g_hist for the next
// graph replay (its last reader, k_thresh, has already run).
// ------------------------------------------------------------------
__global__ void __launch_bounds__(256)
k_compact(int n, int n4) {
    const int gid = blockIdx.x * 256 + threadIdx.x;
    if (gid < NBINS) g_hist[gid] = 0u;

    const unsigned tb = g_thresh_bin;
    const float4* w4 = reinterpret_cast<const float4*>(g_w);
    const int stride = gridDim.x * 256;
    for (int i = gid; i < n4; i += stride) {
        float4 v = w4[i];
        if ((__float_as_uint(v.x) >> 19) >= tb) {
            unsigned p = atomicAdd(&g_ncand, 1u);
            if (p < CAND_CAP) g_cand[p] = 4 * i;
        }
        if ((__float_as_uint(v.y) >> 19) >= tb) {
            unsigned p = atomicAdd(&g_ncand, 1u);
            if (p < CAND_CAP) g_cand[p] = 4 * i + 1;
        }
        if ((__float_as_uint(v.z) >> 19) >= tb) {
            unsigned p = atomicAdd(&g_ncand, 1u);
            if (p < CAND_CAP) g_cand[p] = 4 * i + 2;
        }
        if ((__float_as_uint(v.w) >> 19) >= tb) {
            unsigned p = atomicAdd(&g_ncand, 1u);
            if (p < CAND_CAP) g_cand[p] = 4 * i + 3;
        }
    }
    if (gid == 0) {
        for (int i = n4 * 4; i < n; i++) {
            if ((__float_as_uint(g_w[i]) >> 19) >= tb) {
                unsigned p = atomicAdd(&g_ncand, 1u);
                if (p < CAND_CAP) g_cand[p] = i;
            }
        }
    }
}

// ------------------------------------------------------------------
// K4 (1 block): exact top-50 by rank counting (value desc, index asc —
// identical tiebreak to jax.lax.top_k), then two-team gather +
// weighted sum. Re-zeros g_ncand for the next replay.
// ------------------------------------------------------------------
__global__ void __launch_bounds__(256)
k_final(const float* __restrict__ values, float* __restrict__ out) {
    __shared__ float cw[SEL_CAP];
    __shared__ int   ci[SEL_CAP];
    __shared__ float sel_w[KQW];
    __shared__ int   sel_i[KQW];
    __shared__ float part[2 * NCH];

    int nc = (int)min(g_ncand, (unsigned)CAND_CAP);
    if (nc > SEL_CAP) nc = SEL_CAP;

    for (int i = threadIdx.x; i < nc; i += 256) {
        int idx = g_cand[i];
        ci[i] = idx;
        cw[i] = g_w[idx];
    }
    for (int i = threadIdx.x; i < KQW; i += 256) { sel_w[i] = 0.f; sel_i[i] = 0; }
    __syncthreads();
    if (threadIdx.x == 0) g_ncand = 0u;   // clean for next replay

    for (int i = threadIdx.x; i < nc; i += 256) {
        const float wi = cw[i];
        const int   ii = ci[i];
        int rank = 0;
        for (int j = 0; j < nc; j++) {
            float wj = cw[j];
            rank += (wj > wi) || (wj == wi && ci[j] < ii);
        }
        if (rank < KQW) { sel_w[rank] = wi; sel_i[rank] = ii; }
    }
    __syncthreads();

    const int ns  = nc < KQW ? nc : KQW;
    const int ch  = threadIdx.x & (NCH - 1);
    const int tm  = threadIdx.x >> 7;    // two teams over selections
    float a0 = 0.f, a1 = 0.f, a2 = 0.f, a3 = 0.f;
    int j = tm;
    for (; j + 6 < ns; j += 8) {
        a0 += sel_w[j]     * __ldg(&values[(size_t)sel_i[j]     * NCH + ch]);
        a1 += sel_w[j + 2] * __ldg(&values[(size_t)sel_i[j + 2] * NCH + ch]);
        a2 += sel_w[j + 4] * __ldg(&values[(size_t)sel_i[j + 4] * NCH + ch]);
        a3 += sel_w[j + 6] * __ldg(&values[(size_t)sel_i[j + 6] * NCH + ch]);
    }
    for (; j < ns; j += 2)
        a0 += sel_w[j] * __ldg(&values[(size_t)sel_i[j] * NCH + ch]);
    part[tm * NCH + ch] = ((a0 + a1) + (a2 + a3));
    __syncthreads();
    if (threadIdx.x < NCH)
        out[threadIdx.x] = (part[threadIdx.x] + part[NCH + threadIdx.x]) / g_wsum;
}

// ------------------------------------------------------------------
extern "C" void kernel_launch(void* const* d_in, const int* in_sizes, int n_in,
                              void* d_out, int out_size) {
    const float* key    = (const float*)d_in[0];
    const float* keys   = (const float*)d_in[1];
    const float* values = (const float*)d_in[2];
    float* out = (float*)d_out;

    const int n = in_sizes[1] / NCH;   // number of memory rows (1,000,000)

    k_dist   <<<NB_DIST, 256>>>(key, keys, n);
    k_thresh <<<1, 256>>>(NB_DIST);
    k_compact<<<1024, 256>>>(n, n / 4);
    k_final  <<<1, 256>>>(values, out);
}